// round 1
// baseline (speedup 1.0000x reference)
#include <cuda_runtime.h>
#include <cuda_bf16.h>

// ---------------- scratch (device globals; no allocation allowed) ----------
__device__ float g_buf0[64 * 64 * 64 * 64];   // ec0 out / dt1 out  (16.7M)
__device__ float g_buf1[64 * 128 * 32 * 32];  // main 128-ch stream (8.39M)
__device__ float g_buf2[64 * 128 * 32 * 32];  // resblock temp
__device__ float g_z[64 * 32 * 32 * 32];      // encoder latent
__device__ float g_q[64 * 32 * 32 * 32];      // quantized latent
__device__ float g_loss[1];

// ---------------- ec0: 3->64, k4 s2 p1, in 128x128 -> 64x64, relu ----------
__global__ void conv_ec0(const float* __restrict__ x, const float* __restrict__ w,
                         const float* __restrict__ b, float* __restrict__ out) {
    int idx = blockIdx.x * 256 + threadIdx.x;
    if (idx >= 64 * 64 * 64 * 64) return;
    int ow = idx & 63, oh = (idx >> 6) & 63, co = (idx >> 12) & 63, n = idx >> 18;
    float acc = __ldg(&b[co]);
    #pragma unroll
    for (int ci = 0; ci < 3; ci++) {
        const float* xp = x + ((n * 3 + ci) << 14);
        const float* wp = w + (co * 3 + ci) * 16;
        #pragma unroll
        for (int kh = 0; kh < 4; kh++) {
            int ih = 2 * oh - 1 + kh;
            if ((unsigned)ih < 128u) {
                #pragma unroll
                for (int kw = 0; kw < 4; kw++) {
                    int iw = 2 * ow - 1 + kw;
                    if ((unsigned)iw < 128u)
                        acc += __ldg(&xp[(ih << 7) + iw]) * __ldg(&wp[kh * 4 + kw]);
                }
            }
        }
    }
    out[idx] = fmaxf(acc, 0.f);
}

// ---------------- ec1: 64->128, k4 s2 p1, 64x64 -> 32x32, relu, tiled ------
// block: (n, co_block of 8, 8 output rows). threads 256.
// thread: 2 px (rows rh, rh+4) x 4 co. ci processed in 2 chunks of 32.
__global__ void conv_ec1(const float* __restrict__ in, const float* __restrict__ w,
                         const float* __restrict__ b, float* __restrict__ out) {
    extern __shared__ float sm[];
    float* w_s  = sm;              // 8 * 512
    float* in_s = sm + 8 * 512;    // 32 * 18 * 67 = 38592
    const int n = blockIdx.x, co0 = blockIdx.y * 8, r0 = blockIdx.z * 8;
    const int tid = threadIdx.x;
    const int c = tid & 31, rh = (tid >> 5) & 3, co_l = tid >> 7;
    float acc0[4], acc1[4];
    #pragma unroll
    for (int j = 0; j < 4; j++) acc0[j] = acc1[j] = __ldg(&b[co0 + co_l * 4 + j]);
    const int ih0 = 2 * r0 - 1;
    for (int ch = 0; ch < 2; ch++) {
        for (int t = tid; t < 8 * 512; t += 256) {
            int col = t >> 9, rest = t & 511;
            w_s[t] = w[(co0 + col) * 1024 + ch * 512 + rest];
        }
        for (int t = tid; t < 32 * 18 * 67; t += 256) {
            int ci = t / 1206; int rem = t - ci * 1206;
            int rr = rem / 67;  int cc = rem - rr * 67;
            int ih = ih0 + rr, iw = cc - 1;
            float v = 0.f;
            if ((unsigned)ih < 64u && (unsigned)iw < 64u)
                v = in[((n * 64 + ch * 32 + ci) << 12) + (ih << 6) + iw];
            in_s[t] = v;
        }
        __syncthreads();
        const float* ip0 = in_s + (2 * rh) * 67 + 2 * c;
        const float* wp  = w_s + co_l * 4 * 512;
        for (int ci = 0; ci < 32; ci++) {
            #pragma unroll
            for (int k = 0; k < 16; k++) {
                int off = ci * 1206 + (k >> 2) * 67 + (k & 3);
                float iv0 = ip0[off], iv1 = ip0[off + 8 * 67];
                int wo = ci * 16 + k;
                #pragma unroll
                for (int j = 0; j < 4; j++) {
                    float wv = wp[j * 512 + wo];
                    acc0[j] += iv0 * wv;
                    acc1[j] += iv1 * wv;
                }
            }
        }
        __syncthreads();
    }
    #pragma unroll
    for (int j = 0; j < 4; j++) {
        int co = co0 + co_l * 4 + j;
        int oi0 = ((n * 128 + co) << 10) + ((r0 + rh) << 5) + c;
        out[oi0]       = fmaxf(acc0[j], 0.f);
        out[oi0 + 128] = fmaxf(acc1[j], 0.f);  // +4 rows
    }
}

// ---------------- generic stride-1 conv on 32x32 (KS = 1 or 3), tiled ------
// block: (n, co_block of 8, 8 output rows). threads 256.
// thread: 2 px (rows rh, rh+4) x 4 co.
template <int CIN, int KS>
__global__ void conv_s1(const float* __restrict__ in, const float* __restrict__ w,
                        const float* __restrict__ b, float* __restrict__ out,
                        const float* __restrict__ resid, int Cout,
                        int relu_in, int relu_out) {
    constexpr int PAD = KS / 2;
    constexpr int TIH = 8 + 2 * PAD;
    constexpr int TIW = 32 + 2 * PAD;
    constexpr int WSZ = CIN * KS * KS;
    extern __shared__ float sm[];
    float* w_s  = sm;             // 8 * WSZ
    float* in_s = sm + 8 * WSZ;   // CIN * TIH * TIW
    const int n = blockIdx.x, co0 = blockIdx.y * 8, r0 = blockIdx.z * 8;
    const int tid = threadIdx.x;
    for (int t = tid; t < 8 * WSZ; t += 256) w_s[t] = w[co0 * WSZ + t];
    for (int t = tid; t < CIN * TIH * TIW; t += 256) {
        int ci = t / (TIH * TIW); int rem = t - ci * (TIH * TIW);
        int rr = rem / TIW;       int cc = rem - rr * TIW;
        int ih = r0 - PAD + rr, iw = cc - PAD;
        float v = 0.f;
        if ((unsigned)ih < 32u && (unsigned)iw < 32u) {
            v = in[((n * CIN + ci) << 10) + (ih << 5) + iw];
            if (relu_in) v = fmaxf(v, 0.f);
        }
        in_s[t] = v;
    }
    __syncthreads();
    const int c = tid & 31, rh = (tid >> 5) & 3, co_l = tid >> 7;
    float acc0[4], acc1[4];
    #pragma unroll
    for (int j = 0; j < 4; j++) acc0[j] = acc1[j] = __ldg(&b[co0 + co_l * 4 + j]);
    const float* ip0 = in_s + rh * TIW + c;
    const float* wp  = w_s + (co_l * 4) * WSZ;
    for (int ci = 0; ci < CIN; ci++) {
        #pragma unroll
        for (int k = 0; k < KS * KS; k++) {
            int off = ci * (TIH * TIW) + (k / KS) * TIW + (k % KS);
            float iv0 = ip0[off], iv1 = ip0[off + 4 * TIW];
            int wo = ci * KS * KS + k;
            #pragma unroll
            for (int j = 0; j < 4; j++) {
                float wv = wp[j * WSZ + wo];
                acc0[j] += iv0 * wv;
                acc1[j] += iv1 * wv;
            }
        }
    }
    #pragma unroll
    for (int j = 0; j < 4; j++) {
        int co = co0 + co_l * 4 + j;
        int oi0 = ((n * Cout + co) << 10) + ((r0 + rh) << 5) + c;
        int oi1 = oi0 + 128;  // +4 rows
        float v0 = acc0[j], v1 = acc1[j];
        if (resid) { v0 += resid[oi0]; v1 += resid[oi1]; }
        if (relu_out) { v0 = fmaxf(v0, 0.f); v1 = fmaxf(v1, 0.f); }
        out[oi0] = v0; out[oi1] = v1;
    }
}

// ---------------- vector quantizer + loss ----------------------------------
__global__ void zero_loss_k(float* loss) { loss[0] = 0.f; }

__global__ void vq_kernel(const float* __restrict__ z, const float* __restrict__ emb,
                          float* __restrict__ q, float* __restrict__ loss) {
    extern __shared__ float sm[];
    float* emb_s = sm;             // 512*32
    float* e2_s  = sm + 512 * 32;  // 512
    __shared__ float red[256];
    const int tid = threadIdx.x;
    for (int t = tid; t < 512 * 32; t += 256) emb_s[t] = emb[t];
    __syncthreads();
    for (int k = tid; k < 512; k += 256) {
        float s = 0.f;
        #pragma unroll
        for (int d = 0; d < 32; d++) { float e = emb_s[k * 32 + d]; s += e * e; }
        e2_s[k] = s;
    }
    __syncthreads();
    const int row = blockIdx.x * 256 + tid;   // < 65536
    const int n = row >> 10, hw = row & 1023;
    const float* zp = z + n * 32768 + hw;
    float zv[32];
    #pragma unroll
    for (int d = 0; d < 32; d++) zv[d] = zp[d * 1024];
    float best = 3.4e38f; int bidx = 0;
    for (int k = 0; k < 512; k++) {
        const float* ep = emb_s + k * 32;
        float dot = 0.f;
        #pragma unroll
        for (int d = 0; d < 32; d++) dot += zv[d] * ep[d];
        float dist = e2_s[k] - 2.f * dot;   // + ||z||^2 constant per row
        if (dist < best) { best = dist; bidx = k; }
    }
    float* qp = q + n * 32768 + hw;
    const float* ep = emb_s + bidx * 32;
    float lsum = 0.f;
    #pragma unroll
    for (int d = 0; d < 32; d++) {
        float qv = ep[d];
        qp[d * 1024] = qv;
        float df = qv - zv[d];
        lsum += df * df;
    }
    red[tid] = lsum; __syncthreads();
    for (int s = 128; s > 0; s >>= 1) {
        if (tid < s) red[tid] += red[tid + s];
        __syncthreads();
    }
    if (tid == 0) atomicAdd(loss, red[0]);
}

__global__ void write_loss_k(const float* __restrict__ loss, float* __restrict__ out, int pos) {
    out[pos] = loss[0] * (1.25f / (65536.f * 32.f));
}

// ---------------- dt1: ConvT 128->64, k4 s2 p1, 32x32 -> 64x64, relu -------
// block: (n, co_block of 8, 4 output rows). threads 256.
// thread: 2 px (rows rh, rh+2 within the 4-row tile) x 4 co.
__global__ void convT_dt1(const float* __restrict__ in, const float* __restrict__ w,
                          const float* __restrict__ b, float* __restrict__ out) {
    extern __shared__ float sm[];
    float* w_s  = sm;            // 128 * 128 (= 128ci x 8co x 16)
    float* in_s = sm + 16384;    // 128 * 4 * 34
    const int n = blockIdx.x, co0 = blockIdx.y * 8, oh0 = blockIdx.z * 4;
    const int tid = threadIdx.x;
    for (int t = tid; t < 128 * 128; t += 256) {
        int ci = t >> 7, rest = t & 127;
        w_s[t] = w[(ci << 10) + (co0 << 4) + rest];  // w[ci][co][kh][kw]
    }
    const int ih0 = (oh0 >> 1) - 1;
    for (int t = tid; t < 128 * 4 * 34; t += 256) {
        int ci = t / 136; int rem = t - ci * 136;
        int rr = rem / 34; int cc = rem - rr * 34;
        int ih = ih0 + rr, iw = cc - 1;
        float v = 0.f;
        if ((unsigned)ih < 32u && (unsigned)iw < 32u)
            v = in[((n * 128 + ci) << 10) + (ih << 5) + iw];
        in_s[t] = v;
    }
    __syncthreads();
    const int c = tid & 63, rh = (tid >> 6) & 1, co_l = tid >> 7;
    const int oh_a = oh0 + rh;            // second row: oh_a + 2 (same parity)
    const int qw = (c + 1) & 1, qh = (oh_a + 1) & 1;
    int kw_[2] = {qw, qw + 2};
    int kh_[2] = {qh, qh + 2};
    int lc[2], lra[2];
    #pragma unroll
    for (int t2 = 0; t2 < 2; t2++) {
        lc[t2]  = ((c + 1 - kw_[t2]) >> 1) + 1;            // local col (padded)
        lra[t2] = ((oh_a + 1 - kh_[t2]) >> 1) - ih0;       // local row for oh_a
    }
    float acc0[4], acc1[4];
    #pragma unroll
    for (int j = 0; j < 4; j++) acc0[j] = acc1[j] = __ldg(&b[co0 + co_l * 4 + j]);
    for (int ci = 0; ci < 128; ci++) {
        const float* ip = in_s + ci * 136;
        const float* wp = w_s + (ci << 7) + ((co_l * 4) << 4);
        #pragma unroll
        for (int a = 0; a < 2; a++) {
            #pragma unroll
            for (int bb = 0; bb < 2; bb++) {
                float iva = ip[lra[a] * 34 + lc[bb]];
                float ivb = ip[(lra[a] + 1) * 34 + lc[bb]];  // row oh_a+2
                int k = (kh_[a] << 2) + kw_[bb];
                #pragma unroll
                for (int j = 0; j < 4; j++) {
                    float wv = wp[(j << 4) + k];
                    acc0[j] += iva * wv;
                    acc1[j] += ivb * wv;
                }
            }
        }
    }
    #pragma unroll
    for (int j = 0; j < 4; j++) {
        int co = co0 + co_l * 4 + j;
        int base = ((n * 64 + co) << 12) + (oh_a << 6) + c;
        out[base]             = fmaxf(acc0[j], 0.f);
        out[base + (2 << 6)]  = fmaxf(acc1[j], 0.f);
    }
}

// ---------------- dt2: ConvT 64->3, k4 s2 p1, 64x64 -> 128x128 -------------
__global__ void convT_dt2(const float* __restrict__ in, const float* __restrict__ w,
                          const float* __restrict__ b, float* __restrict__ out) {
    int idx = blockIdx.x * 256 + threadIdx.x;
    if (idx >= 64 * 3 * 128 * 128) return;
    int ow = idx & 127, oh = (idx >> 7) & 127;
    int nc = idx >> 14; int co = nc % 3; int n = nc / 3;
    int qh = (oh + 1) & 1, qw = (ow + 1) & 1;
    float acc = __ldg(&b[co]);
    #pragma unroll
    for (int a = 0; a < 2; a++) {
        int kh = qh + 2 * a, ih = (oh + 1 - kh) >> 1;
        if ((unsigned)ih >= 64u) continue;
        #pragma unroll
        for (int bb = 0; bb < 2; bb++) {
            int kw = qw + 2 * bb, iw = (ow + 1 - kw) >> 1;
            if ((unsigned)iw >= 64u) continue;
            const float* ip = in + (n << 18) + (ih << 6) + iw;   // n*64*64*64
            const float* wp = w + (co << 4) + (kh << 2) + kw;    // w[ci][co][kh][kw], ci stride 48
            #pragma unroll 4
            for (int ci = 0; ci < 64; ci++)
                acc += __ldg(&ip[ci << 12]) * __ldg(&wp[ci * 48]);
        }
    }
    out[idx] = acc;
}

// ---------------- launch ----------------------------------------------------
extern "C" void kernel_launch(void* const* d_in, const int* in_sizes, int n_in,
                              void* d_out, int out_size) {
    const float* x      = (const float*)d_in[0];
    const float* ec0_w  = (const float*)d_in[1];  const float* ec0_b = (const float*)d_in[2];
    const float* ec1_w  = (const float*)d_in[3];  const float* ec1_b = (const float*)d_in[4];
    const float* er1a_w = (const float*)d_in[5];  const float* er1a_b = (const float*)d_in[6];
    const float* er1b_w = (const float*)d_in[7];  const float* er1b_b = (const float*)d_in[8];
    const float* er2a_w = (const float*)d_in[9];  const float* er2a_b = (const float*)d_in[10];
    const float* er2b_w = (const float*)d_in[11]; const float* er2b_b = (const float*)d_in[12];
    const float* ec2_w  = (const float*)d_in[13]; const float* ec2_b  = (const float*)d_in[14];
    const float* emb    = (const float*)d_in[15];
    const float* dc0_w  = (const float*)d_in[16]; const float* dc0_b  = (const float*)d_in[17];
    const float* dr1a_w = (const float*)d_in[18]; const float* dr1a_b = (const float*)d_in[19];
    const float* dr1b_w = (const float*)d_in[20]; const float* dr1b_b = (const float*)d_in[21];
    const float* dr2a_w = (const float*)d_in[22]; const float* dr2a_b = (const float*)d_in[23];
    const float* dr2b_w = (const float*)d_in[24]; const float* dr2b_b = (const float*)d_in[25];
    const float* dt1_w  = (const float*)d_in[26]; const float* dt1_b  = (const float*)d_in[27];
    const float* dt2_w  = (const float*)d_in[28]; const float* dt2_b  = (const float*)d_in[29];
    float* out = (float*)d_out;

    float *buf0, *buf1, *buf2, *zb, *qb, *lossb;
    cudaGetSymbolAddress((void**)&buf0, g_buf0);
    cudaGetSymbolAddress((void**)&buf1, g_buf1);
    cudaGetSymbolAddress((void**)&buf2, g_buf2);
    cudaGetSymbolAddress((void**)&zb, g_z);
    cudaGetSymbolAddress((void**)&qb, g_q);
    cudaGetSymbolAddress((void**)&lossb, g_loss);

    const int SMEM_EC1   = (8 * 512 + 32 * 18 * 67) * 4;          // 170752
    const int SMEM_C128_3 = (8 * 1152 + 128 * 10 * 34) * 4;       // 210944
    const int SMEM_C128_1 = (8 * 128 + 128 * 8 * 32) * 4;         // 135168
    const int SMEM_C32_3  = (8 * 288 + 32 * 10 * 34) * 4;         // 52736
    const int SMEM_DT1    = (128 * 128 + 128 * 4 * 34) * 4;       // 135168
    const int SMEM_VQ     = (512 * 32 + 512) * 4;                 // 67584

    cudaFuncSetAttribute(conv_ec1,        cudaFuncAttributeMaxDynamicSharedMemorySize, SMEM_EC1);
    cudaFuncSetAttribute(conv_s1<128, 3>, cudaFuncAttributeMaxDynamicSharedMemorySize, SMEM_C128_3);
    cudaFuncSetAttribute(conv_s1<128, 1>, cudaFuncAttributeMaxDynamicSharedMemorySize, SMEM_C128_1);
    cudaFuncSetAttribute(conv_s1<32, 3>,  cudaFuncAttributeMaxDynamicSharedMemorySize, SMEM_C32_3);
    cudaFuncSetAttribute(convT_dt1,       cudaFuncAttributeMaxDynamicSharedMemorySize, SMEM_DT1);
    cudaFuncSetAttribute(vq_kernel,       cudaFuncAttributeMaxDynamicSharedMemorySize, SMEM_VQ);

    // ---- encoder ----
    conv_ec0<<<(64 * 64 * 64 * 64) / 256, 256>>>(x, ec0_w, ec0_b, buf0);
    conv_ec1<<<dim3(64, 16, 4), 256, SMEM_EC1>>>(buf0, ec1_w, ec1_b, buf1);
    // res1: buf2 = relu(conv3x3(relu(buf1))); buf1 += conv1x1(buf2)
    conv_s1<128, 3><<<dim3(64, 16, 4), 256, SMEM_C128_3>>>(buf1, er1a_w, er1a_b, buf2, nullptr, 128, 1, 1);
    conv_s1<128, 1><<<dim3(64, 16, 4), 256, SMEM_C128_1>>>(buf2, er1b_w, er1b_b, buf1, buf1, 128, 0, 0);
    // res2
    conv_s1<128, 3><<<dim3(64, 16, 4), 256, SMEM_C128_3>>>(buf1, er2a_w, er2a_b, buf2, nullptr, 128, 1, 1);
    conv_s1<128, 1><<<dim3(64, 16, 4), 256, SMEM_C128_1>>>(buf2, er2b_w, er2b_b, buf1, buf1, 128, 0, 0);
    // ec2: 128 -> 32
    conv_s1<128, 3><<<dim3(64, 4, 4), 256, SMEM_C128_3>>>(buf1, ec2_w, ec2_b, zb, nullptr, 32, 0, 0);

    // ---- vector quantizer ----
    zero_loss_k<<<1, 1>>>(lossb);
    vq_kernel<<<256, 256, SMEM_VQ>>>(zb, emb, qb, lossb);

    // ---- decoder ----
    conv_s1<32, 3><<<dim3(64, 16, 4), 256, SMEM_C32_3>>>(qb, dc0_w, dc0_b, buf1, nullptr, 128, 0, 0);
    conv_s1<128, 3><<<dim3(64, 16, 4), 256, SMEM_C128_3>>>(buf1, dr1a_w, dr1a_b, buf2, nullptr, 128, 1, 1);
    conv_s1<128, 1><<<dim3(64, 16, 4), 256, SMEM_C128_1>>>(buf2, dr1b_w, dr1b_b, buf1, buf1, 128, 0, 0);
    conv_s1<128, 3><<<dim3(64, 16, 4), 256, SMEM_C128_3>>>(buf1, dr2a_w, dr2a_b, buf2, nullptr, 128, 1, 1);
    conv_s1<128, 1><<<dim3(64, 16, 4), 256, SMEM_C128_1>>>(buf2, dr2b_w, dr2b_b, buf1, buf1, 128, 0, 0);
    convT_dt1<<<dim3(64, 8, 16), 256, SMEM_DT1>>>(buf1, dt1_w, dt1_b, buf0);
    convT_dt2<<<(64 * 3 * 128 * 128) / 256, 256>>>(buf0, dt2_w, dt2_b, out);

    // loss scalar goes last in the flattened output
    write_loss_k<<<1, 1>>>(lossb, out, out_size - 1);
}

// round 5
// speedup vs baseline: 1.3102x; 1.3102x over previous
#include <cuda_runtime.h>
#include <cuda_bf16.h>

// ---------------- scratch (device globals; no allocation allowed) ----------
__device__ float g_buf0[64 * 64 * 64 * 64];   // ec0 out / dt1 out  (16.7M)
__device__ float g_buf1[64 * 128 * 32 * 32];  // main 128-ch stream
__device__ float g_buf2[64 * 128 * 32 * 32];  // resblock temp
__device__ float g_z[64 * 32 * 32 * 32];      // encoder latent
__device__ float g_q[64 * 32 * 32 * 32];      // quantized latent
__device__ float g_loss[1];

// align a float-offset up to a multiple of 4 (16 bytes) for float4 LDS.128
#define ALIGN4(x) (((x) + 3) & ~3)

// ======================= stride-1 conv on 32x32 (KS = 1 or 3) ==============
// block tile: 16 co x 8 rows x 32 cols. 256 threads.
// thread: 4 co x (2 rows x 2 cols). ci chunked by 16.
template <int CIN, int KS>
__global__ void conv_s1(const float* __restrict__ in, const float* __restrict__ w,
                        const float* __restrict__ b, float* __restrict__ out,
                        const float* __restrict__ resid, int Cout,
                        int relu_in, int relu_out) {
    constexpr int PAD = KS / 2;
    constexpr int TIH = 8 + 2 * PAD;
    constexpr int TIW = 32 + 2 * PAD;
    constexpr int TIWP = TIW | 1;      // odd pitch: 35 or 33
    constexpr int KK = KS * KS;
    constexpr int CHUNK = 16;
    constexpr int WROW = 20;
    constexpr int IN_SZ = ALIGN4(CHUNK * TIH * TIWP);
    extern __shared__ float sm[];
    float* in_s = sm;                // CHUNK*TIH*TIWP
    float* w_s  = sm + IN_SZ;        // CHUNK*KK*WROW (16B aligned)

    const int n = blockIdx.x, co0 = blockIdx.y * 16, r0 = blockIdx.z * 8;
    const int tid = threadIdx.x;
    const int col_l = tid & 15, row_l = (tid >> 4) & 3, co_l = tid >> 6;

    float acc[4][4];
    #pragma unroll
    for (int j = 0; j < 4; j++) {
        float bv = __ldg(&b[co0 + co_l * 4 + j]);
        acc[j][0] = acc[j][1] = acc[j][2] = acc[j][3] = bv;
    }

    for (int ch = 0; ch < CIN / CHUNK; ch++) {
        for (int t = tid; t < CHUNK * TIH * TIW; t += 256) {
            int ci = t / (TIH * TIW); int rem = t - ci * (TIH * TIW);
            int rr = rem / TIW, cc = rem - rr * TIW;
            int ih = r0 - PAD + rr, iw = cc - PAD;
            float v = 0.f;
            if ((unsigned)ih < 32u && (unsigned)iw < 32u) {
                v = in[((n * CIN + ch * CHUNK + ci) << 10) + (ih << 5) + iw];
                if (relu_in) v = fmaxf(v, 0.f);
            }
            in_s[ci * (TIH * TIWP) + rr * TIWP + cc] = v;
        }
        for (int t = tid; t < 16 * CHUNK * KK; t += 256) {
            int col = t / (CHUNK * KK); int rem = t - col * (CHUNK * KK);
            w_s[rem * WROW + col] = w[(co0 + col) * CIN * KK + ch * CHUNK * KK + rem];
        }
        __syncthreads();

        const float* ibase = in_s + (row_l * 2) * TIWP + col_l * 2;
        #pragma unroll 2
        for (int ci = 0; ci < CHUNK; ci++) {
            const float* ip = ibase + ci * (TIH * TIWP);
            const float* wp = w_s + ci * KK * WROW + co_l * 4;
            #pragma unroll
            for (int k = 0; k < KK; k++) {
                const float4 wv = *reinterpret_cast<const float4*>(wp + k * WROW);
                const float* q = ip + (k / KS) * TIWP + (k % KS);
                float i00 = q[0], i01 = q[1], i10 = q[TIWP], i11 = q[TIWP + 1];
                acc[0][0] += wv.x * i00; acc[0][1] += wv.x * i01;
                acc[0][2] += wv.x * i10; acc[0][3] += wv.x * i11;
                acc[1][0] += wv.y * i00; acc[1][1] += wv.y * i01;
                acc[1][2] += wv.y * i10; acc[1][3] += wv.y * i11;
                acc[2][0] += wv.z * i00; acc[2][1] += wv.z * i01;
                acc[2][2] += wv.z * i10; acc[2][3] += wv.z * i11;
                acc[3][0] += wv.w * i00; acc[3][1] += wv.w * i01;
                acc[3][2] += wv.w * i10; acc[3][3] += wv.w * i11;
            }
        }
        __syncthreads();
    }

    #pragma unroll
    for (int j = 0; j < 4; j++) {
        int co = co0 + co_l * 4 + j;
        int base = ((n * Cout + co) << 10) + ((r0 + row_l * 2) << 5) + col_l * 2;
        #pragma unroll
        for (int rr = 0; rr < 2; rr++) {
            float v0 = acc[j][rr * 2], v1 = acc[j][rr * 2 + 1];
            if (resid) {
                float2 rv = *reinterpret_cast<const float2*>(&resid[base + rr * 32]);
                v0 += rv.x; v1 += rv.y;
            }
            if (relu_out) { v0 = fmaxf(v0, 0.f); v1 = fmaxf(v1, 0.f); }
            float2 ov = make_float2(v0, v1);
            *reinterpret_cast<float2*>(&out[base + rr * 32]) = ov;
        }
    }
}

// ======================= ec1: 64->128, k4 s2 p1, 64x64 -> 32x32, relu ======
__global__ void conv_ec1(const float* __restrict__ in, const float* __restrict__ w,
                         const float* __restrict__ b, float* __restrict__ out) {
    constexpr int CHUNK = 8;
    constexpr int IN_SZ = ALIGN4(CHUNK * 18 * 67);
    extern __shared__ float sm[];
    float* in_s = sm;              // 8 * 18 * 67
    float* w_s  = sm + IN_SZ;      // 8*16*20
    const int n = blockIdx.x, co0 = blockIdx.y * 16, r0 = blockIdx.z * 8;
    const int tid = threadIdx.x;
    const int col_l = tid & 15, row_l = (tid >> 4) & 3, co_l = tid >> 6;

    float acc[4][4];
    #pragma unroll
    for (int j = 0; j < 4; j++) {
        float bv = __ldg(&b[co0 + co_l * 4 + j]);
        acc[j][0] = acc[j][1] = acc[j][2] = acc[j][3] = bv;
    }
    const int ih0 = 2 * r0 - 1;

    for (int ch = 0; ch < 8; ch++) {
        for (int t = tid; t < CHUNK * 18 * 66; t += 256) {
            int ci = t / (18 * 66); int rem = t - ci * (18 * 66);
            int rr = rem / 66, cc = rem - rr * 66;
            int ih = ih0 + rr, iw = cc - 1;
            float v = 0.f;
            if ((unsigned)ih < 64u && (unsigned)iw < 64u)
                v = in[((n * 64 + ch * CHUNK + ci) << 12) + (ih << 6) + iw];
            in_s[ci * (18 * 67) + rr * 67 + (cc & 1) * 33 + (cc >> 1)] = v;
        }
        for (int t = tid; t < 16 * CHUNK * 16; t += 256) {
            int col = t / (CHUNK * 16); int rem = t - col * (CHUNK * 16);
            w_s[rem * 20 + col] = w[(co0 + col) * 64 * 16 + ch * CHUNK * 16 + rem];
        }
        __syncthreads();

        for (int ci = 0; ci < CHUNK; ci++) {
            const float* ibase = in_s + ci * (18 * 67);
            const float* wbase = w_s + ci * 16 * 20 + co_l * 4;
            #pragma unroll
            for (int kh = 0; kh < 4; kh++) {
                int rA = 4 * row_l + kh;
                #pragma unroll
                for (int kw = 0; kw < 4; kw++) {
                    const float4 wv = *reinterpret_cast<const float4*>(wbase + (kh * 4 + kw) * 20);
                    int p = kw & 1, h = 2 * col_l + (kw >> 1);
                    const float* q = ibase + rA * 67 + p * 33 + h;
                    float iA0 = q[0], iA1 = q[1], iB0 = q[134], iB1 = q[135];
                    acc[0][0] += wv.x * iA0; acc[0][1] += wv.x * iA1;
                    acc[0][2] += wv.x * iB0; acc[0][3] += wv.x * iB1;
                    acc[1][0] += wv.y * iA0; acc[1][1] += wv.y * iA1;
                    acc[1][2] += wv.y * iB0; acc[1][3] += wv.y * iB1;
                    acc[2][0] += wv.z * iA0; acc[2][1] += wv.z * iA1;
                    acc[2][2] += wv.z * iB0; acc[2][3] += wv.z * iB1;
                    acc[3][0] += wv.w * iA0; acc[3][1] += wv.w * iA1;
                    acc[3][2] += wv.w * iB0; acc[3][3] += wv.w * iB1;
                }
            }
        }
        __syncthreads();
    }

    const int rA = r0 + 2 * row_l, c = 2 * col_l;
    #pragma unroll
    for (int j = 0; j < 4; j++) {
        int co = co0 + co_l * 4 + j;
        int base = ((n * 128 + co) << 10) + (rA << 5) + c;
        float2 v0 = make_float2(fmaxf(acc[j][0], 0.f), fmaxf(acc[j][1], 0.f));
        float2 v1 = make_float2(fmaxf(acc[j][2], 0.f), fmaxf(acc[j][3], 0.f));
        *reinterpret_cast<float2*>(&out[base]) = v0;
        *reinterpret_cast<float2*>(&out[base + 32]) = v1;
    }
}

// ======================= ec0: 3->64, k4 s2 p1, 128x128 -> 64x64, relu ======
__global__ void conv_ec0(const float* __restrict__ in, const float* __restrict__ w,
                         const float* __restrict__ b, float* __restrict__ out) {
    constexpr int IN_SZ = ALIGN4(3 * 18 * 67);   // 3618 -> 3620 (16B aligned)
    extern __shared__ float sm[];
    float* in_s = sm;               // 3 * 18 * 67
    float* w_s  = sm + IN_SZ;       // 3*16*20
    const int n = blockIdx.x, co0 = blockIdx.y * 16;
    const int rblk = blockIdx.z >> 1, cblk = blockIdx.z & 1;
    const int r0 = rblk * 8, c0 = cblk * 32;
    const int tid = threadIdx.x;
    const int col_l = tid & 15, row_l = (tid >> 4) & 3, co_l = tid >> 6;

    const int ih0 = 2 * r0 - 1, iw0 = 2 * c0 - 1;
    for (int t = tid; t < 3 * 18 * 66; t += 256) {
        int ci = t / (18 * 66); int rem = t - ci * (18 * 66);
        int rr = rem / 66, cc = rem - rr * 66;
        int ih = ih0 + rr, iw = iw0 + cc;
        float v = 0.f;
        if ((unsigned)ih < 128u && (unsigned)iw < 128u)
            v = in[((n * 3 + ci) << 14) + (ih << 7) + iw];
        in_s[ci * (18 * 67) + rr * 67 + (cc & 1) * 33 + (cc >> 1)] = v;
    }
    for (int t = tid; t < 16 * 48; t += 256) {
        int col = t / 48; int rem = t - col * 48;
        w_s[rem * 20 + col] = w[(co0 + col) * 48 + rem];
    }
    __syncthreads();

    float acc[4][4];
    #pragma unroll
    for (int j = 0; j < 4; j++) {
        float bv = __ldg(&b[co0 + co_l * 4 + j]);
        acc[j][0] = acc[j][1] = acc[j][2] = acc[j][3] = bv;
    }
    #pragma unroll
    for (int ci = 0; ci < 3; ci++) {
        const float* ibase = in_s + ci * (18 * 67);
        const float* wbase = w_s + ci * 16 * 20 + co_l * 4;
        #pragma unroll
        for (int kh = 0; kh < 4; kh++) {
            int rA = 4 * row_l + kh;
            #pragma unroll
            for (int kw = 0; kw < 4; kw++) {
                const float4 wv = *reinterpret_cast<const float4*>(wbase + (kh * 4 + kw) * 20);
                int p = kw & 1, h = 2 * col_l + (kw >> 1);
                const float* q = ibase + rA * 67 + p * 33 + h;
                float iA0 = q[0], iA1 = q[1], iB0 = q[134], iB1 = q[135];
                acc[0][0] += wv.x * iA0; acc[0][1] += wv.x * iA1;
                acc[0][2] += wv.x * iB0; acc[0][3] += wv.x * iB1;
                acc[1][0] += wv.y * iA0; acc[1][1] += wv.y * iA1;
                acc[1][2] += wv.y * iB0; acc[1][3] += wv.y * iB1;
                acc[2][0] += wv.z * iA0; acc[2][1] += wv.z * iA1;
                acc[2][2] += wv.z * iB0; acc[2][3] += wv.z * iB1;
                acc[3][0] += wv.w * iA0; acc[3][1] += wv.w * iA1;
                acc[3][2] += wv.w * iB0; acc[3][3] += wv.w * iB1;
            }
        }
    }
    const int rA = r0 + 2 * row_l, c = c0 + 2 * col_l;
    #pragma unroll
    for (int j = 0; j < 4; j++) {
        int co = co0 + co_l * 4 + j;
        int base = ((n * 64 + co) << 12) + (rA << 6) + c;
        float2 v0 = make_float2(fmaxf(acc[j][0], 0.f), fmaxf(acc[j][1], 0.f));
        float2 v1 = make_float2(fmaxf(acc[j][2], 0.f), fmaxf(acc[j][3], 0.f));
        *reinterpret_cast<float2*>(&out[base]) = v0;
        *reinterpret_cast<float2*>(&out[base + 64]) = v1;
    }
}

// ======================= vector quantizer + loss ===========================
__global__ void zero_loss_k(float* loss) { loss[0] = 0.f; }

__global__ void vq_kernel(const float* __restrict__ z, const float* __restrict__ emb,
                          float* __restrict__ q, float* __restrict__ loss) {
    extern __shared__ float sm[];
    float* emb_s = sm;             // 512*32
    float* e2_s  = sm + 512 * 32;  // 512
    __shared__ float red[256];
    const int tid = threadIdx.x;
    for (int t = tid; t < 512 * 32; t += 256) emb_s[t] = emb[t];
    __syncthreads();
    for (int k = tid; k < 512; k += 256) {
        float s = 0.f;
        #pragma unroll
        for (int d = 0; d < 32; d++) { float e = emb_s[k * 32 + d]; s += e * e; }
        e2_s[k] = s;
    }
    __syncthreads();
    const int row = blockIdx.x * 256 + tid;
    const int n = row >> 10, hw = row & 1023;
    const float* zp = z + n * 32768 + hw;
    float zv[32];
    #pragma unroll
    for (int d = 0; d < 32; d++) zv[d] = zp[d * 1024];
    float best = 3.4e38f; int bidx = 0;
    for (int k = 0; k < 512; k++) {
        const float4* ep = reinterpret_cast<const float4*>(emb_s + k * 32);
        float dot = 0.f;
        #pragma unroll
        for (int d = 0; d < 8; d++) {
            float4 e4 = ep[d];
            dot += zv[d * 4] * e4.x + zv[d * 4 + 1] * e4.y
                 + zv[d * 4 + 2] * e4.z + zv[d * 4 + 3] * e4.w;
        }
        float dist = e2_s[k] - 2.f * dot;
        if (dist < best) { best = dist; bidx = k; }
    }
    float* qp = q + n * 32768 + hw;
    const float* ep = emb_s + bidx * 32;
    float lsum = 0.f;
    #pragma unroll
    for (int d = 0; d < 32; d++) {
        float qv = ep[d];
        qp[d * 1024] = qv;
        float df = qv - zv[d];
        lsum += df * df;
    }
    red[tid] = lsum; __syncthreads();
    for (int s = 128; s > 0; s >>= 1) {
        if (tid < s) red[tid] += red[tid + s];
        __syncthreads();
    }
    if (tid == 0) atomicAdd(loss, red[0]);
}

__global__ void write_loss_k(const float* __restrict__ loss, float* __restrict__ out, int pos) {
    out[pos] = loss[0] * (1.25f / (65536.f * 32.f));
}

// ======================= dt1: ConvT 128->64, k4 s2 p1, 32x32 -> 64x64 ======
__global__ void convT_dt1(const float* __restrict__ in, const float* __restrict__ w,
                          const float* __restrict__ b, float* __restrict__ out) {
    constexpr int CHUNK = 16;
    constexpr int IN_SZ = ALIGN4(CHUNK * 6 * 19);
    extern __shared__ float sm[];
    float* in_s = sm;              // 16*6*19
    float* w_s  = sm + IN_SZ;      // 16*16*20
    const int n = blockIdx.x, co0 = blockIdx.y * 16;
    const int rblk = blockIdx.z >> 1, cblk = blockIdx.z & 1;
    const int R0 = rblk * 4, C0 = cblk * 16;   // half-res tile origin
    const int tid = threadIdx.x;
    const int col_l = tid & 15, row_l = (tid >> 4) & 3, co_l = tid >> 6;

    float acc[4][4];
    #pragma unroll
    for (int j = 0; j < 4; j++) {
        float bv = __ldg(&b[co0 + co_l * 4 + j]);
        acc[j][0] = acc[j][1] = acc[j][2] = acc[j][3] = bv;
    }

    for (int ch = 0; ch < 8; ch++) {
        for (int t = tid; t < CHUNK * 6 * 18; t += 256) {
            int ci = t / 108; int rem = t - ci * 108;
            int rr = rem / 18, cc = rem - rr * 18;
            int ih = R0 - 1 + rr, iw = C0 - 1 + cc;
            float v = 0.f;
            if ((unsigned)ih < 32u && (unsigned)iw < 32u)
                v = in[((n * 128 + ch * CHUNK + ci) << 10) + (ih << 5) + iw];
            in_s[ci * 114 + rr * 19 + cc] = v;
        }
        for (int t = tid; t < CHUNK * 256; t += 256) {
            int ci = t >> 8; int rem = t & 255;
            int col = rem >> 4, k = rem & 15;
            w_s[(ci * 16 + k) * 20 + col] = w[(ch * CHUNK + ci) * 1024 + (co0 + col) * 16 + k];
        }
        __syncthreads();

        for (int ci = 0; ci < CHUNK; ci++) {
            const float* ip = in_s + ci * 114 + row_l * 19 + col_l;
            float i00 = ip[0],  i01 = ip[1],  i02 = ip[2];
            float i10 = ip[19], i11 = ip[20], i12 = ip[21];
            float i20 = ip[38], i21 = ip[39], i22 = ip[40];
            const float* wp = w_s + ci * 320 + co_l * 4;
            #define DT1_T(K, IV, PX) { const float4 wv = *reinterpret_cast<const float4*>(wp + (K) * 20); \
                acc[0][PX] += wv.x * (IV); acc[1][PX] += wv.y * (IV); \
                acc[2][PX] += wv.z * (IV); acc[3][PX] += wv.w * (IV); }
            DT1_T(5,  i11, 0) DT1_T(7,  i10, 0) DT1_T(13, i01, 0) DT1_T(15, i00, 0)
            DT1_T(4,  i12, 1) DT1_T(6,  i11, 1) DT1_T(12, i02, 1) DT1_T(14, i01, 1)
            DT1_T(1,  i21, 2) DT1_T(3,  i20, 2) DT1_T(9,  i11, 2) DT1_T(11, i10, 2)
            DT1_T(0,  i22, 3) DT1_T(2,  i21, 3) DT1_T(8,  i12, 3) DT1_T(10, i11, 3)
            #undef DT1_T
        }
        __syncthreads();
    }

    const int oh = 2 * (R0 + row_l), ow = 2 * (C0 + col_l);
    #pragma unroll
    for (int j = 0; j < 4; j++) {
        int co = co0 + co_l * 4 + j;
        int base = ((n * 64 + co) << 12) + (oh << 6) + ow;
        float2 v0 = make_float2(fmaxf(acc[j][0], 0.f), fmaxf(acc[j][1], 0.f));
        float2 v1 = make_float2(fmaxf(acc[j][2], 0.f), fmaxf(acc[j][3], 0.f));
        *reinterpret_cast<float2*>(&out[base]) = v0;
        *reinterpret_cast<float2*>(&out[base + 64]) = v1;
    }
}

// ======================= dt2: ConvT 64->3, k4 s2 p1, 64x64 -> 128x128 ======
__global__ void convT_dt2(const float* __restrict__ in, const float* __restrict__ w,
                          const float* __restrict__ b, float* __restrict__ out) {
    constexpr int CHUNK = 16;
    constexpr int IN_SZ = ALIGN4(CHUNK * 6 * 67);
    extern __shared__ float sm[];
    float* in_s = sm;              // 16*6*67
    float* w_s  = sm + IN_SZ;      // 16*16*4
    const int n = blockIdx.x;
    const int R0 = blockIdx.y * 4;      // half-res row origin (out rows 8)
    const int tid = threadIdx.x;
    const int col_l = tid & 63, row_l = tid >> 6;

    float acc[3][4];
    #pragma unroll
    for (int j = 0; j < 3; j++) {
        float bv = __ldg(&b[j]);
        acc[j][0] = acc[j][1] = acc[j][2] = acc[j][3] = bv;
    }

    for (int ch = 0; ch < 4; ch++) {
        for (int t = tid; t < CHUNK * 6 * 66; t += 256) {
            int ci = t / 396; int rem = t - ci * 396;
            int rr = rem / 66, cc = rem - rr * 66;
            int ih = R0 - 1 + rr, iw = cc - 1;
            float v = 0.f;
            if ((unsigned)ih < 64u && (unsigned)iw < 64u)
                v = in[((n * 64 + ch * CHUNK + ci) << 12) + (ih << 6) + iw];
            in_s[ci * 402 + rr * 67 + cc] = v;
        }
        for (int t = tid; t < CHUNK * 48; t += 256) {
            int ci = t / 48; int rem = t - ci * 48;
            int col = rem >> 4, k = rem & 15;
            w_s[(ci * 16 + k) * 4 + col] = w[(ch * CHUNK + ci) * 48 + col * 16 + k];
        }
        __syncthreads();

        for (int ci = 0; ci < CHUNK; ci++) {
            const float* ip = in_s + ci * 402 + row_l * 67 + col_l;
            float i00 = ip[0],   i01 = ip[1],   i02 = ip[2];
            float i10 = ip[67],  i11 = ip[68],  i12 = ip[69];
            float i20 = ip[134], i21 = ip[135], i22 = ip[136];
            const float* wp = w_s + ci * 64;
            #define DT2_T(K, IV, PX) { const float4 wv = *reinterpret_cast<const float4*>(wp + (K) * 4); \
                acc[0][PX] += wv.x * (IV); acc[1][PX] += wv.y * (IV); acc[2][PX] += wv.z * (IV); }
            DT2_T(5,  i11, 0) DT2_T(7,  i10, 0) DT2_T(13, i01, 0) DT2_T(15, i00, 0)
            DT2_T(4,  i12, 1) DT2_T(6,  i11, 1) DT2_T(12, i02, 1) DT2_T(14, i01, 1)
            DT2_T(1,  i21, 2) DT2_T(3,  i20, 2) DT2_T(9,  i11, 2) DT2_T(11, i10, 2)
            DT2_T(0,  i22, 3) DT2_T(2,  i21, 3) DT2_T(8,  i12, 3) DT2_T(10, i11, 3)
            #undef DT2_T
        }
        __syncthreads();
    }

    const int oh = 2 * (R0 + row_l), ow = 2 * col_l;
    #pragma unroll
    for (int j = 0; j < 3; j++) {
        int base = ((n * 3 + j) << 14) + (oh << 7) + ow;
        float2 v0 = make_float2(acc[j][0], acc[j][1]);
        float2 v1 = make_float2(acc[j][2], acc[j][3]);
        *reinterpret_cast<float2*>(&out[base]) = v0;
        *reinterpret_cast<float2*>(&out[base + 128]) = v1;
    }
}

// ======================= launch ============================================
extern "C" void kernel_launch(void* const* d_in, const int* in_sizes, int n_in,
                              void* d_out, int out_size) {
    const float* x      = (const float*)d_in[0];
    const float* ec0_w  = (const float*)d_in[1];  const float* ec0_b = (const float*)d_in[2];
    const float* ec1_w  = (const float*)d_in[3];  const float* ec1_b = (const float*)d_in[4];
    const float* er1a_w = (const float*)d_in[5];  const float* er1a_b = (const float*)d_in[6];
    const float* er1b_w = (const float*)d_in[7];  const float* er1b_b = (const float*)d_in[8];
    const float* er2a_w = (const float*)d_in[9];  const float* er2a_b = (const float*)d_in[10];
    const float* er2b_w = (const float*)d_in[11]; const float* er2b_b = (const float*)d_in[12];
    const float* ec2_w  = (const float*)d_in[13]; const float* ec2_b  = (const float*)d_in[14];
    const float* emb    = (const float*)d_in[15];
    const float* dc0_w  = (const float*)d_in[16]; const float* dc0_b  = (const float*)d_in[17];
    const float* dr1a_w = (const float*)d_in[18]; const float* dr1a_b = (const float*)d_in[19];
    const float* dr1b_w = (const float*)d_in[20]; const float* dr1b_b = (const float*)d_in[21];
    const float* dr2a_w = (const float*)d_in[22]; const float* dr2a_b = (const float*)d_in[23];
    const float* dr2b_w = (const float*)d_in[24]; const float* dr2b_b = (const float*)d_in[25];
    const float* dt1_w  = (const float*)d_in[26]; const float* dt1_b  = (const float*)d_in[27];
    const float* dt2_w  = (const float*)d_in[28]; const float* dt2_b  = (const float*)d_in[29];
    float* out = (float*)d_out;

    float *buf0, *buf1, *buf2, *zb, *qb, *lossb;
    cudaGetSymbolAddress((void**)&buf0, g_buf0);
    cudaGetSymbolAddress((void**)&buf1, g_buf1);
    cudaGetSymbolAddress((void**)&buf2, g_buf2);
    cudaGetSymbolAddress((void**)&zb, g_z);
    cudaGetSymbolAddress((void**)&qb, g_q);
    cudaGetSymbolAddress((void**)&lossb, g_loss);

    const int SM_C3  = (ALIGN4(16 * 10 * 35) + 16 * 9 * 20) * 4;
    const int SM_C1  = (ALIGN4(16 * 8 * 33) + 16 * 20) * 4;
    const int SM_EC1 = (ALIGN4(8 * 18 * 67) + 8 * 16 * 20) * 4;
    const int SM_EC0 = (ALIGN4(3 * 18 * 67) + 3 * 16 * 20) * 4;
    const int SM_DT1 = (ALIGN4(16 * 6 * 19) + 16 * 16 * 20) * 4;
    const int SM_DT2 = (ALIGN4(16 * 6 * 67) + 16 * 16 * 4) * 4;
    const int SM_VQ  = (512 * 32 + 512) * 4;

    cudaFuncSetAttribute(conv_s1<128, 3>, cudaFuncAttributeMaxDynamicSharedMemorySize, SM_C3);
    cudaFuncSetAttribute(conv_s1<32, 3>,  cudaFuncAttributeMaxDynamicSharedMemorySize, SM_C3);
    cudaFuncSetAttribute(conv_s1<128, 1>, cudaFuncAttributeMaxDynamicSharedMemorySize, SM_C1);
    cudaFuncSetAttribute(conv_ec1,        cudaFuncAttributeMaxDynamicSharedMemorySize, SM_EC1);
    cudaFuncSetAttribute(conv_ec0,        cudaFuncAttributeMaxDynamicSharedMemorySize, SM_EC0);
    cudaFuncSetAttribute(convT_dt1,       cudaFuncAttributeMaxDynamicSharedMemorySize, SM_DT1);
    cudaFuncSetAttribute(convT_dt2,       cudaFuncAttributeMaxDynamicSharedMemorySize, SM_DT2);
    cudaFuncSetAttribute(vq_kernel,       cudaFuncAttributeMaxDynamicSharedMemorySize, SM_VQ);

    // ---- encoder ----
    conv_ec0<<<dim3(64, 4, 16), 256, SM_EC0>>>(x, ec0_w, ec0_b, buf0);
    conv_ec1<<<dim3(64, 8, 4), 256, SM_EC1>>>(buf0, ec1_w, ec1_b, buf1);
    conv_s1<128, 3><<<dim3(64, 8, 4), 256, SM_C3>>>(buf1, er1a_w, er1a_b, buf2, nullptr, 128, 1, 1);
    conv_s1<128, 1><<<dim3(64, 8, 4), 256, SM_C1>>>(buf2, er1b_w, er1b_b, buf1, buf1, 128, 0, 0);
    conv_s1<128, 3><<<dim3(64, 8, 4), 256, SM_C3>>>(buf1, er2a_w, er2a_b, buf2, nullptr, 128, 1, 1);
    conv_s1<128, 1><<<dim3(64, 8, 4), 256, SM_C1>>>(buf2, er2b_w, er2b_b, buf1, buf1, 128, 0, 0);
    conv_s1<128, 3><<<dim3(64, 2, 4), 256, SM_C3>>>(buf1, ec2_w, ec2_b, zb, nullptr, 32, 0, 0);

    // ---- vector quantizer ----
    zero_loss_k<<<1, 1>>>(lossb);
    vq_kernel<<<256, 256, SM_VQ>>>(zb, emb, qb, lossb);

    // ---- decoder ----
    conv_s1<32, 3><<<dim3(64, 8, 4), 256, SM_C3>>>(qb, dc0_w, dc0_b, buf1, nullptr, 128, 0, 0);
    conv_s1<128, 3><<<dim3(64, 8, 4), 256, SM_C3>>>(buf1, dr1a_w, dr1a_b, buf2, nullptr, 128, 1, 1);
    conv_s1<128, 1><<<dim3(64, 8, 4), 256, SM_C1>>>(buf2, dr1b_w, dr1b_b, buf1, buf1, 128, 0, 0);
    conv_s1<128, 3><<<dim3(64, 8, 4), 256, SM_C3>>>(buf1, dr2a_w, dr2a_b, buf2, nullptr, 128, 1, 1);
    conv_s1<128, 1><<<dim3(64, 8, 4), 256, SM_C1>>>(buf2, dr2b_w, dr2b_b, buf1, buf1, 128, 0, 0);
    convT_dt1<<<dim3(64, 4, 16), 256, SM_DT1>>>(buf1, dt1_w, dt1_b, buf0);
    convT_dt2<<<dim3(64, 16), 256, SM_DT2>>>(buf0, dt2_w, dt2_b, out);

    write_loss_k<<<1, 1>>>(lossb, out, out_size - 1);
}